// round 16
// baseline (speedup 1.0000x reference)
#include <cuda_runtime.h>
#include <cuda_fp16.h>
#include <cstdint>
#include <math.h>

// ---------------------------------------------------------------------------
// GraphSAGE fraud detector — round 15.
//  * GEMM2: CTA 128x256 with 512 threads (16 warps @ 64x32) — same per-SM
//    warp count as 2x(128x128) but A-operand re-reads halved (grid.y 4->2).
//  * GEMM1 keeps the 128x128 / 2-CTA-per-SM shape.
//  * Fused decoupled-lookback scan; sigmoid fused into GEMM2 epilogue.
// ---------------------------------------------------------------------------

#define MAXN 50048
#define MAXE 409600
#define HDIM 512
#define FDIM 128

#define STAGES   3
#define ASTAGE   8192                       // 128 rows x 32 fp16

#define SCANB    1024
#define NSCANB   ((MAXN + SCANB - 1) / SCANB)
#define NDONE    512
#define AGGF     0x40000000
#define PREF     0x80000000u
#define VMASK    0x0FFFFFFF

__device__ __align__(16) float  g_inv[MAXN];
__device__ __align__(16) __half g_xh [(size_t)MAXN * FDIM];
__device__ __align__(16) __half g_ag1[(size_t)MAXN * FDIM];
__device__ __align__(16) __half g_h1 [(size_t)MAXN * HDIM];
__device__ __align__(16) __half g_ag2[(size_t)MAXN * HDIM];
__device__ __align__(16) __half g_w1h[(size_t)HDIM * 256];
__device__ __align__(16) __half g_w2h[(size_t)HDIM * 1024];
__device__ int g_aux[MAXN + NSCANB + NDONE];
__device__ int g_off[MAXN + 1];
__device__ int g_eid[MAXE];

// ======================= helpers =============================

__device__ __forceinline__ uint32_t smem_u32(const void* p) {
    uint32_t a;
    asm("{ .reg .u64 t; cvta.to.shared.u64 t, %1; cvt.u32.u64 %0, t; }"
        : "=r"(a) : "l"(p));
    return a;
}

__device__ __forceinline__ void ldsm4(uint32_t* r, uint32_t addr) {
    asm volatile("ldmatrix.sync.aligned.m8n8.x4.shared.b16 {%0,%1,%2,%3}, [%4];"
                 : "=r"(r[0]), "=r"(r[1]), "=r"(r[2]), "=r"(r[3]) : "r"(addr));
}

__device__ __forceinline__ void mma16816(float* d, const uint32_t* a, const uint32_t* b) {
    asm volatile(
        "mma.sync.aligned.m16n8k16.row.col.f32.f16.f16.f32 "
        "{%0,%1,%2,%3}, {%4,%5,%6,%7}, {%8,%9}, {%0,%1,%2,%3};"
        : "+f"(d[0]), "+f"(d[1]), "+f"(d[2]), "+f"(d[3])
        : "r"(a[0]), "r"(a[1]), "r"(a[2]), "r"(a[3]), "r"(b[0]), "r"(b[1]));
}

__device__ __forceinline__ void cp16(uint32_t dst, const void* src, int src_sz) {
    asm volatile("cp.async.cg.shared.global [%0], [%1], 16, %2;"
                 :: "r"(dst), "l"(src), "r"(src_sz) : "memory");
}

#define CP_COMMIT() asm volatile("cp.async.commit_group;" ::: "memory")
#define CP_WAIT1()  asm volatile("cp.async.wait_group 1;" ::: "memory")

__device__ __forceinline__ uint32_t pack_h2(float a, float b) {
    __half2 h = __floats2half2_rn(a, b);
    return *(uint32_t*)&h;
}

__device__ __forceinline__ uint32_t taddr(int r, int c16) {
    return (uint32_t)((r >> 1) * 128 + ((((r & 1) * 4 + c16) ^ ((r >> 1) & 7)) << 4));
}

// ============== fused convert + aux clear (cnt, scan state, done) ==========

__global__ void tohalf_all(const float* __restrict__ x,  __half* __restrict__ xh,  int nx4,
                           const float* __restrict__ w1, __half* __restrict__ w1h, int nw14,
                           const float* __restrict__ w2, __half* __restrict__ w2h, int nw24,
                           int* __restrict__ aux, int naux) {
    int i = blockIdx.x * blockDim.x + threadIdx.x;
    const int tot = nx4 + nw14 + nw24;
    if (i < tot) {
        const float* sp; __half* dp;
        if (i < nx4)             { sp = x;  dp = xh; }
        else if (i < nx4 + nw14) { sp = w1; dp = w1h; i -= nx4; }
        else                     { sp = w2; dp = w2h; i -= nx4 + nw14; }
        float4 v = ((const float4*)sp)[i];
        uint2 o;
        o.x = pack_h2(v.x, v.y);
        o.y = pack_h2(v.z, v.w);
        ((uint2*)dp)[i] = o;
    } else {
        int j = i - tot;
        if (j < naux) aux[j] = 0;
    }
}

// ======================= CSR build =============================

__global__ void count_kernel(const int* __restrict__ dst, int E, int* __restrict__ cnt) {
    int e = blockIdx.x * blockDim.x + threadIdx.x;
    if (e < E) atomicAdd(&cnt[dst[e]], 1);
}

// Single-kernel scan with decoupled lookback. state[] pre-zeroed.
__global__ void scan_fused(int* __restrict__ cnt, int* __restrict__ off,
                           float* __restrict__ inv, volatile int* state,
                           int n, int nblocks) {
    __shared__ int wsum[32];
    __shared__ int sh_tot, sh_pfx;
    const int t    = threadIdx.x;
    const int lane = t & 31;
    const int wid  = t >> 5;
    const int b    = blockIdx.x;
    const int i    = b * SCANB + t;

    int c = 0;
    if (i < n) {
        c = cnt[i];
        cnt[i] = 0;
        inv[i] = 1.0f / fmaxf((float)c, 1.0f);
    }
    int v = c;
#pragma unroll
    for (int o = 1; o < 32; o <<= 1) {
        int u = __shfl_up_sync(0xffffffffu, v, o);
        if (lane >= o) v += u;
    }
    if (lane == 31) wsum[wid] = v;
    __syncthreads();
    if (wid == 0) {
        int w = wsum[lane];
#pragma unroll
        for (int o = 1; o < 32; o <<= 1) {
            int u = __shfl_up_sync(0xffffffffu, w, o);
            if (lane >= o) w += u;
        }
        wsum[lane] = w;
    }
    __syncthreads();
    const int wexcl = (wid == 0) ? 0 : wsum[wid - 1];
    const int local = wexcl + v - c;
    if (t == 1023) sh_tot = wexcl + v;
    __syncthreads();
    const int total = sh_tot;

    if (wid == 0) {
        if (b == 0) {
            if (lane == 0) {
                sh_pfx = 0;
                atomicExch((int*)&state[0], (int)(PREF | (unsigned)total));
            }
        } else {
            if (lane == 0) atomicExch((int*)&state[b], AGGF | total);
            int pfx = 0;
            int j = b - 1;
            for (;;) {
                const int idx = j - lane;
                int s = 0;
                if (idx >= 0) { do { s = state[idx]; } while (s == 0); }
                const unsigned pmask =
                    __ballot_sync(0xffffffffu, idx >= 0 && ((unsigned)s & PREF));
                int contrib;
                bool done;
                if (pmask) {
                    const int plane = __ffs(pmask) - 1;
                    contrib = (lane <= plane && idx >= 0) ? (s & VMASK) : 0;
                    done = true;
                } else {
                    contrib = (idx >= 0) ? (s & VMASK) : 0;
                    done = false;
                }
#pragma unroll
                for (int o = 16; o; o >>= 1)
                    contrib += __shfl_xor_sync(0xffffffffu, contrib, o);
                pfx += contrib;
                if (done) break;
                j -= 32;
            }
            if (lane == 0) {
                sh_pfx = pfx;
                atomicExch((int*)&state[b], (int)(PREF | (unsigned)(pfx + total)));
            }
        }
    }
    __syncthreads();
    const int pfx = sh_pfx;
    if (i < n) off[i] = local + pfx;
    if (b == nblocks - 1 && t == 1023) off[n] = pfx + total;
}

__global__ void fill_kernel(const int* __restrict__ src, const int* __restrict__ dst,
                            int E, const int* __restrict__ off,
                            int* __restrict__ pos, int* __restrict__ eid) {
    int e = blockIdx.x * blockDim.x + threadIdx.x;
    if (e < E) {
        int d = dst[e];
        int p = atomicAdd(&pos[d], 1);
        eid[off[d] + p] = src[e];
    }
}

// ---------------- CSR gather (fp16): mean of incoming features -------------
template <int U>
__global__ void gather_f16(const __half* __restrict__ feat,
                           const int* __restrict__ off,
                           const int* __restrict__ eid,
                           const float* __restrict__ inv,
                           __half* __restrict__ outp, int N,
                           const float* __restrict__ bo, float* __restrict__ outInit) {
    const int g = blockIdx.x * (256 / U) + threadIdx.x / U;
    const int c = threadIdx.x % U;
    if (g >= N) return;
    if (bo != nullptr && c == 0) outInit[g] = bo[0];
    const int b  = off[g];
    const int e2 = off[g + 1];
    float acc[8];
#pragma unroll
    for (int q = 0; q < 8; ++q) acc[q] = 0.f;
    const uint4* base = (const uint4*)feat;
#pragma unroll 4
    for (int j = b; j < e2; ++j) {
        int s = __ldg(&eid[j]);
        uint4 u = __ldg(&base[(long long)s * U + c]);
        const __half2* h = (const __half2*)&u;
#pragma unroll
        for (int q = 0; q < 4; ++q) {
            float2 f = __half22float2(h[q]);
            acc[2 * q]     += f.x;
            acc[2 * q + 1] += f.y;
        }
    }
    const float sc = inv[g];
    uint4 o;
    o.x = pack_h2(acc[0] * sc, acc[1] * sc);
    o.y = pack_h2(acc[2] * sc, acc[3] * sc);
    o.z = pack_h2(acc[4] * sc, acc[5] * sc);
    o.w = pack_h2(acc[6] * sc, acc[7] * sc);
    ((uint4*)outp)[(long long)g * U + c] = o;
}

// =================== mma.sync fp16 concat-GEMM =============================
// BN=128: 256 thr, 8 warps @64x32, 2 CTAs/SM (layer 1).
// BN=256: 512 thr, 16 warps @64x32, 1 CTA/SM — halves A re-reads (layer 2).
// FUSED 0: epilogue bias+ReLU -> fp16 C.
// FUSED 1: epilogue head + completion counter -> fused sigmoid.

template <int FUSED, int BN>
__global__ void __launch_bounds__(BN == 128 ? 256 : 512, BN == 128 ? 2 : 1)
gemm_f16(const __half* __restrict__ A1, const __half* __restrict__ A2,
         const __half* __restrict__ W,
         const float* __restrict__ bias, __half* __restrict__ C,
         const float* __restrict__ Wo, float* __restrict__ outLogit,
         int* __restrict__ done, int M, int Kh) {
    constexpr int NT     = (BN == 128) ? 256 : 512;   // threads
    constexpr int BSTG   = BN * 64;                   // B stage bytes (BN rows x 32 fp16)
    extern __shared__ __align__(128) uint8_t dynsmem[];
    const uint32_t sbA = smem_u32(dynsmem);
    const uint32_t sbB = sbA + STAGES * ASTAGE;

    const int tid  = threadIdx.x;
    const int wid  = tid >> 5;
    const int lane = tid & 31;
    const int wm   = wid & 1;        // 2 M bands of 64
    const int wn   = wid >> 1;       // BN/32 N bands
    const int K    = 2 * Kh;
    const int m0   = blockIdx.x * 128;
    const int n0   = blockIdx.y * BN;

    const int qrow = lane & 15;
    const int qsel = lane >> 4;

    float acc[4][4][4];
#pragma unroll
    for (int i = 0; i < 4; ++i)
#pragma unroll
        for (int j = 0; j < 4; ++j)
#pragma unroll
            for (int r = 0; r < 4; ++r) acc[i][j][r] = 0.0f;

    const int nch = K >> 5;

    auto issue_chunk = [&](int ch, int st) {
        const int k0 = ch << 5;
        const bool useA2 = (k0 >= Kh);
        const int koff = useA2 ? k0 - Kh : k0;
        const __half* Ab = useA2 ? A2 : A1;
        const uint32_t abase = sbA + st * ASTAGE;
        const uint32_t bbase = sbB + st * BSTG;
        // A: 512 16B units
#pragma unroll
        for (int u0 = 0; u0 < 512 / NT; ++u0) {
            const int u = tid + u0 * NT;
            const int row = u >> 2, c16 = u & 3;
            const int m = m0 + row;
            const void* src = Ab + (long long)m * Kh + koff + c16 * 8;
            cp16(abase + taddr(row, c16), src, (m < M) ? 16 : 0);
        }
        // B: BN*4 16B units
#pragma unroll
        for (int u0 = 0; u0 < (BN * 4) / NT; ++u0) {
            const int u = tid + u0 * NT;
            const int row = u >> 2, c16 = u & 3;
            const void* src = W + (long long)(n0 + row) * K + k0 + c16 * 8;
            cp16(bbase + taddr(row, c16), src, 16);
        }
    };

    issue_chunk(0, 0); CP_COMMIT();
    issue_chunk(1, 1); CP_COMMIT();

    for (int ch = 0; ch < nch; ++ch) {
        CP_WAIT1();
        __syncthreads();
        {
            const int nxt = ch + STAGES - 1;
            if (nxt < nch) issue_chunk(nxt, nxt % STAGES);
            CP_COMMIT();
        }

        const int st = ch % STAGES;
        const uint32_t aST = sbA + st * ASTAGE;
        const uint32_t bST = sbB + st * BSTG;

#pragma unroll
        for (int s = 0; s < 2; ++s) {
            const int cc = s * 2 + qsel;
            uint32_t ah[4][4], bh[2][4];
#pragma unroll
            for (int i = 0; i < 4; ++i)
                ldsm4(ah[i], aST + taddr(wm * 64 + i * 16 + qrow, cc));
#pragma unroll
            for (int p = 0; p < 2; ++p)
                ldsm4(bh[p], bST + taddr(wn * 32 + p * 16 + qrow, cc));
#pragma unroll
            for (int i = 0; i < 4; ++i) {
#pragma unroll
                for (int p = 0; p < 2; ++p) {
                    uint32_t f0[2] = { bh[p][0], bh[p][2] };
                    uint32_t f1[2] = { bh[p][1], bh[p][3] };
                    mma16816(acc[i][2 * p],     ah[i], f0);
                    mma16816(acc[i][2 * p + 1], ah[i], f1);
                }
            }
        }
    }
    __syncthreads();

    if (FUSED == 0) {
#pragma unroll
        for (int j = 0; j < 4; ++j) {
            const int nb = n0 + wn * 32 + j * 8 + (lane & 3) * 2;
            const float b0f = bias[nb], b1f = bias[nb + 1];
#pragma unroll
            for (int i = 0; i < 4; ++i) {
                const int r0 = m0 + wm * 64 + i * 16 + (lane >> 2);
                if (r0 < M) {
                    *(uint32_t*)(C + (long long)r0 * HDIM + nb) =
                        pack_h2(fmaxf(acc[i][j][0] + b0f, 0.f),
                                fmaxf(acc[i][j][1] + b1f, 0.f));
                }
                const int r1 = r0 + 8;
                if (r1 < M) {
                    *(uint32_t*)(C + (long long)r1 * HDIM + nb) =
                        pack_h2(fmaxf(acc[i][j][2] + b0f, 0.f),
                                fmaxf(acc[i][j][3] + b1f, 0.f));
                }
            }
        }
    } else {
#pragma unroll
        for (int i = 0; i < 4; ++i) {
            float p0 = 0.f, p1 = 0.f;
#pragma unroll
            for (int j = 0; j < 4; ++j) {
                const int nb = n0 + wn * 32 + j * 8 + (lane & 3) * 2;
                const float b0f = bias[nb],  b1f = bias[nb + 1];
                const float w0 = __ldg(&Wo[nb]), w1 = __ldg(&Wo[nb + 1]);
                p0 += fmaxf(acc[i][j][0] + b0f, 0.f) * w0
                    + fmaxf(acc[i][j][1] + b1f, 0.f) * w1;
                p1 += fmaxf(acc[i][j][2] + b0f, 0.f) * w0
                    + fmaxf(acc[i][j][3] + b1f, 0.f) * w1;
            }
            p0 += __shfl_xor_sync(0xffffffffu, p0, 1);
            p0 += __shfl_xor_sync(0xffffffffu, p0, 2);
            p1 += __shfl_xor_sync(0xffffffffu, p1, 1);
            p1 += __shfl_xor_sync(0xffffffffu, p1, 2);
            if ((lane & 3) == 0) {
                const int r0 = m0 + wm * 64 + i * 16 + (lane >> 2);
                const int r1 = r0 + 8;
                if (r0 < M) atomicAdd(&outLogit[r0], p0);
                if (r1 < M) atomicAdd(&outLogit[r1], p1);
            }
        }
        // ---- completion counter: last n-band CTA applies sigmoid ----
        __threadfence();
        __syncthreads();
        __shared__ int sh_old;
        if (tid == 0) sh_old = atomicAdd(&done[blockIdx.x], 1);
        __syncthreads();
        if (sh_old == (int)gridDim.y - 1 && tid < 128) {
            const int m = m0 + tid;
            if (m < M) {
                volatile float* vo = outLogit;
                float z = vo[m];
                vo[m] = 1.0f / (1.0f + expf(-z));
            }
        }
    }
}

// ---------------- launch ----------------

extern "C" void kernel_launch(void* const* d_in, const int* in_sizes, int n_in,
                              void* d_out, int out_size) {
    const float* x  = (const float*)d_in[0];
    const int*   ei = (const int*)  d_in[1];
    const float* W1 = (const float*)d_in[2];
    const float* b1 = (const float*)d_in[3];
    const float* W2 = (const float*)d_in[4];
    const float* b2 = (const float*)d_in[5];
    const float* Wo = (const float*)d_in[6];
    const float* bo = (const float*)d_in[7];
    float* out = (float*)d_out;

    const int N = in_sizes[0] / FDIM;
    const int E = in_sizes[1] / 2;
    const int* src = ei;
    const int* dst = ei + E;

    float *inv;
    __half *xh, *ag1, *h1, *ag2, *w1h, *w2h;
    int *aux, *off, *eid;
    cudaGetSymbolAddress((void**)&inv, g_inv);
    cudaGetSymbolAddress((void**)&xh,  g_xh);
    cudaGetSymbolAddress((void**)&ag1, g_ag1);
    cudaGetSymbolAddress((void**)&h1,  g_h1);
    cudaGetSymbolAddress((void**)&ag2, g_ag2);
    cudaGetSymbolAddress((void**)&w1h, g_w1h);
    cudaGetSymbolAddress((void**)&w2h, g_w2h);
    cudaGetSymbolAddress((void**)&aux, g_aux);
    cudaGetSymbolAddress((void**)&off, g_off);
    cudaGetSymbolAddress((void**)&eid, g_eid);

    const int nscan = (N + SCANB - 1) / SCANB;
    int* cnt   = aux;
    int* state = aux + MAXN;
    int* done  = aux + MAXN + NSCANB;

    const int SM1 = STAGES * (ASTAGE + 128 * 64);   // 49152
    const int SM2 = STAGES * (ASTAGE + 256 * 64);   // 73728
    cudaFuncSetAttribute((const void*)gemm_f16<0, 128>,
                         cudaFuncAttributeMaxDynamicSharedMemorySize, SM1);
    cudaFuncSetAttribute((const void*)gemm_f16<1, 256>,
                         cudaFuncAttributeMaxDynamicSharedMemorySize, SM2);

    const int T = 256;

    // ---- converts + aux clear ----
    const int nx4  = N * FDIM / 4;
    const int nw14 = HDIM * 2 * FDIM / 4;
    const int nw24 = HDIM * 2 * HDIM / 4;
    const int naux = MAXN + NSCANB + NDONE;
    const int tot  = nx4 + nw14 + nw24 + naux;
    tohalf_all<<<(tot + T - 1) / T, T>>>(x, xh, nx4, W1, w1h, nw14, W2, w2h, nw24, aux, naux);

    // ---- CSR build ----
    count_kernel<<<(E + T - 1) / T, T>>>(dst, E, cnt);
    scan_fused<<<nscan, SCANB>>>(cnt, off, inv, state, N, nscan);
    fill_kernel<<<(E + T - 1) / T, T>>>(src, dst, E, off, cnt, eid);

    // ---- layer 1 ----
    gather_f16<16><<<(N + 15) / 16, 256>>>(xh, off, eid, inv, ag1, N, nullptr, nullptr);
    {
        dim3 grid((N + 127) / 128, HDIM / 128);
        gemm_f16<0, 128><<<grid, 256, SM1>>>(xh, ag1, w1h, b1, h1, nullptr, nullptr,
                                             nullptr, N, FDIM);
    }

    // ---- layer 2 (head + sigmoid fused; gather inits logits to bo) ----
    gather_f16<64><<<(N + 3) / 4, 256>>>(h1, off, eid, inv, ag2, N, bo, out);
    {
        dim3 grid((N + 127) / 128, HDIM / 256);
        gemm_f16<1, 256><<<grid, 512, SM2>>>(h1, ag2, w2h, b2, nullptr, Wo, out,
                                             done, N, HDIM);
    }
}

// round 17
// speedup vs baseline: 1.1286x; 1.1286x over previous
#include <cuda_runtime.h>
#include <cuda_fp16.h>
#include <cstdint>
#include <math.h>

// ---------------------------------------------------------------------------
// GraphSAGE fraud detector — round 16 (convergence).
//  * GEMM restored to the measured-best round-11 shape for BOTH layers:
//    CTA 128x128, warp 64x32, 3-stage cp.async, 2 CTAs/SM.
//  * Gathers: round-11 single-chain form (measured best).
//  * Fused decoupled-lookback scan (1 launch); sigmoid fused into GEMM2.
// ---------------------------------------------------------------------------

#define MAXN 50048
#define MAXE 409600
#define HDIM 512
#define FDIM 128

#define STAGES   3
#define ASTAGE   8192
#define BSTAGE   8192
#define SMEM_TOT (STAGES * (ASTAGE + BSTAGE))   // 49152

#define SCANB    1024
#define NSCANB   ((MAXN + SCANB - 1) / SCANB)
#define NDONE    512
#define AGGF     0x40000000
#define PREF     0x80000000u
#define VMASK    0x0FFFFFFF

__device__ __align__(16) float  g_inv[MAXN];
__device__ __align__(16) __half g_xh [(size_t)MAXN * FDIM];
__device__ __align__(16) __half g_ag1[(size_t)MAXN * FDIM];
__device__ __align__(16) __half g_h1 [(size_t)MAXN * HDIM];
__device__ __align__(16) __half g_ag2[(size_t)MAXN * HDIM];
__device__ __align__(16) __half g_w1h[(size_t)HDIM * 256];
__device__ __align__(16) __half g_w2h[(size_t)HDIM * 1024];
__device__ int g_aux[MAXN + NSCANB + NDONE];
__device__ int g_off[MAXN + 1];
__device__ int g_eid[MAXE];

// ======================= helpers =============================

__device__ __forceinline__ uint32_t smem_u32(const void* p) {
    uint32_t a;
    asm("{ .reg .u64 t; cvta.to.shared.u64 t, %1; cvt.u32.u64 %0, t; }"
        : "=r"(a) : "l"(p));
    return a;
}

__device__ __forceinline__ void ldsm4(uint32_t* r, uint32_t addr) {
    asm volatile("ldmatrix.sync.aligned.m8n8.x4.shared.b16 {%0,%1,%2,%3}, [%4];"
                 : "=r"(r[0]), "=r"(r[1]), "=r"(r[2]), "=r"(r[3]) : "r"(addr));
}

__device__ __forceinline__ void mma16816(float* d, const uint32_t* a, const uint32_t* b) {
    asm volatile(
        "mma.sync.aligned.m16n8k16.row.col.f32.f16.f16.f32 "
        "{%0,%1,%2,%3}, {%4,%5,%6,%7}, {%8,%9}, {%0,%1,%2,%3};"
        : "+f"(d[0]), "+f"(d[1]), "+f"(d[2]), "+f"(d[3])
        : "r"(a[0]), "r"(a[1]), "r"(a[2]), "r"(a[3]), "r"(b[0]), "r"(b[1]));
}

__device__ __forceinline__ void cp16(uint32_t dst, const void* src, int src_sz) {
    asm volatile("cp.async.cg.shared.global [%0], [%1], 16, %2;"
                 :: "r"(dst), "l"(src), "r"(src_sz) : "memory");
}

#define CP_COMMIT() asm volatile("cp.async.commit_group;" ::: "memory")
#define CP_WAIT1()  asm volatile("cp.async.wait_group 1;" ::: "memory")

__device__ __forceinline__ uint32_t pack_h2(float a, float b) {
    __half2 h = __floats2half2_rn(a, b);
    return *(uint32_t*)&h;
}

__device__ __forceinline__ uint32_t taddr(int r, int c16) {
    return (uint32_t)((r >> 1) * 128 + ((((r & 1) * 4 + c16) ^ ((r >> 1) & 7)) << 4));
}

// ============== fused convert + aux clear (cnt, scan state, done) ==========

__global__ void tohalf_all(const float* __restrict__ x,  __half* __restrict__ xh,  int nx4,
                           const float* __restrict__ w1, __half* __restrict__ w1h, int nw14,
                           const float* __restrict__ w2, __half* __restrict__ w2h, int nw24,
                           int* __restrict__ aux, int naux) {
    int i = blockIdx.x * blockDim.x + threadIdx.x;
    const int tot = nx4 + nw14 + nw24;
    if (i < tot) {
        const float* sp; __half* dp;
        if (i < nx4)             { sp = x;  dp = xh; }
        else if (i < nx4 + nw14) { sp = w1; dp = w1h; i -= nx4; }
        else                     { sp = w2; dp = w2h; i -= nx4 + nw14; }
        float4 v = ((const float4*)sp)[i];
        uint2 o;
        o.x = pack_h2(v.x, v.y);
        o.y = pack_h2(v.z, v.w);
        ((uint2*)dp)[i] = o;
    } else {
        int j = i - tot;
        if (j < naux) aux[j] = 0;
    }
}

// ======================= CSR build =============================

__global__ void count_kernel(const int* __restrict__ dst, int E, int* __restrict__ cnt) {
    int e = blockIdx.x * blockDim.x + threadIdx.x;
    if (e < E) atomicAdd(&cnt[dst[e]], 1);
}

// Single-kernel scan with decoupled lookback. state[] pre-zeroed.
__global__ void scan_fused(int* __restrict__ cnt, int* __restrict__ off,
                           float* __restrict__ inv, volatile int* state,
                           int n, int nblocks) {
    __shared__ int wsum[32];
    __shared__ int sh_tot, sh_pfx;
    const int t    = threadIdx.x;
    const int lane = t & 31;
    const int wid  = t >> 5;
    const int b    = blockIdx.x;
    const int i    = b * SCANB + t;

    int c = 0;
    if (i < n) {
        c = cnt[i];
        cnt[i] = 0;
        inv[i] = 1.0f / fmaxf((float)c, 1.0f);
    }
    int v = c;
#pragma unroll
    for (int o = 1; o < 32; o <<= 1) {
        int u = __shfl_up_sync(0xffffffffu, v, o);
        if (lane >= o) v += u;
    }
    if (lane == 31) wsum[wid] = v;
    __syncthreads();
    if (wid == 0) {
        int w = wsum[lane];
#pragma unroll
        for (int o = 1; o < 32; o <<= 1) {
            int u = __shfl_up_sync(0xffffffffu, w, o);
            if (lane >= o) w += u;
        }
        wsum[lane] = w;
    }
    __syncthreads();
    const int wexcl = (wid == 0) ? 0 : wsum[wid - 1];
    const int local = wexcl + v - c;
    if (t == 1023) sh_tot = wexcl + v;
    __syncthreads();
    const int total = sh_tot;

    if (wid == 0) {
        if (b == 0) {
            if (lane == 0) {
                sh_pfx = 0;
                atomicExch((int*)&state[0], (int)(PREF | (unsigned)total));
            }
        } else {
            if (lane == 0) atomicExch((int*)&state[b], AGGF | total);
            int pfx = 0;
            int j = b - 1;
#pragma unroll 1
            for (;;) {
                const int idx = j - lane;
                int s = 0;
                if (idx >= 0) { do { s = state[idx]; } while (s == 0); }
                const unsigned pmask =
                    __ballot_sync(0xffffffffu, idx >= 0 && ((unsigned)s & PREF));
                int contrib;
                bool done;
                if (pmask) {
                    const int plane = __ffs(pmask) - 1;
                    contrib = (lane <= plane && idx >= 0) ? (s & VMASK) : 0;
                    done = true;
                } else {
                    contrib = (idx >= 0) ? (s & VMASK) : 0;
                    done = false;
                }
#pragma unroll
                for (int o = 16; o; o >>= 1)
                    contrib += __shfl_xor_sync(0xffffffffu, contrib, o);
                pfx += contrib;
                if (done) break;
                j -= 32;
            }
            if (lane == 0) {
                sh_pfx = pfx;
                atomicExch((int*)&state[b], (int)(PREF | (unsigned)(pfx + total)));
            }
        }
    }
    __syncthreads();
    const int pfx = sh_pfx;
    if (i < n) off[i] = local + pfx;
    if (b == nblocks - 1 && t == 1023) off[n] = pfx + total;
}

__global__ void fill_kernel(const int* __restrict__ src, const int* __restrict__ dst,
                            int E, const int* __restrict__ off,
                            int* __restrict__ pos, int* __restrict__ eid) {
    int e = blockIdx.x * blockDim.x + threadIdx.x;
    if (e < E) {
        int d = dst[e];
        int p = atomicAdd(&pos[d], 1);
        eid[off[d] + p] = src[e];
    }
}

// ---------------- CSR gather (fp16): mean of incoming features -------------
template <int U>
__global__ void gather_f16(const __half* __restrict__ feat,
                           const int* __restrict__ off,
                           const int* __restrict__ eid,
                           const float* __restrict__ inv,
                           __half* __restrict__ outp, int N,
                           const float* __restrict__ bo, float* __restrict__ outInit) {
    const int g = blockIdx.x * (256 / U) + threadIdx.x / U;
    const int c = threadIdx.x % U;
    if (g >= N) return;
    if (bo != nullptr && c == 0) outInit[g] = bo[0];
    const int b  = off[g];
    const int e2 = off[g + 1];
    float acc[8];
#pragma unroll
    for (int q = 0; q < 8; ++q) acc[q] = 0.f;
    const uint4* base = (const uint4*)feat;
#pragma unroll 4
    for (int j = b; j < e2; ++j) {
        int s = __ldg(&eid[j]);
        uint4 u = __ldg(&base[(long long)s * U + c]);
        const __half2* h = (const __half2*)&u;
#pragma unroll
        for (int q = 0; q < 4; ++q) {
            float2 f = __half22float2(h[q]);
            acc[2 * q]     += f.x;
            acc[2 * q + 1] += f.y;
        }
    }
    const float sc = inv[g];
    uint4 o;
    o.x = pack_h2(acc[0] * sc, acc[1] * sc);
    o.y = pack_h2(acc[2] * sc, acc[3] * sc);
    o.z = pack_h2(acc[4] * sc, acc[5] * sc);
    o.w = pack_h2(acc[6] * sc, acc[7] * sc);
    ((uint4*)outp)[(long long)g * U + c] = o;
}

// =================== mma.sync fp16 concat-GEMM, 3-stage, 2 CTA/SM ==========
// CTA 128(M) x 128(N); 8 warps, each 64x32; K chunks of 32.
// FUSED 0: epilogue bias+ReLU -> fp16 C.
// FUSED 1: epilogue head + completion counter -> fused sigmoid.

template <int FUSED>
__global__ void __launch_bounds__(256, 2)
gemm_f16(const __half* __restrict__ A1, const __half* __restrict__ A2,
         const __half* __restrict__ W,
         const float* __restrict__ bias, __half* __restrict__ C,
         const float* __restrict__ Wo, float* __restrict__ outLogit,
         int* __restrict__ done, int M, int Kh) {
    extern __shared__ __align__(128) uint8_t dynsmem[];
    const uint32_t sbA = smem_u32(dynsmem);
    const uint32_t sbB = sbA + STAGES * ASTAGE;

    const int tid  = threadIdx.x;
    const int wid  = tid >> 5;
    const int lane = tid & 31;
    const int wm   = wid & 1;
    const int wn   = wid >> 1;
    const int K    = 2 * Kh;
    const int m0   = blockIdx.x * 128;
    const int n0   = blockIdx.y * 128;

    const int qrow = lane & 15;
    const int qsel = lane >> 4;

    float acc[4][4][4];
#pragma unroll
    for (int i = 0; i < 4; ++i)
#pragma unroll
        for (int j = 0; j < 4; ++j)
#pragma unroll
            for (int r = 0; r < 4; ++r) acc[i][j][r] = 0.0f;

    const int nch = K >> 5;

    auto issue_chunk = [&](int ch, int st) {
        const int k0 = ch << 5;
        const bool useA2 = (k0 >= Kh);
        const int koff = useA2 ? k0 - Kh : k0;
        const __half* Ab = useA2 ? A2 : A1;
        const uint32_t abase = sbA + st * ASTAGE;
        const uint32_t bbase = sbB + st * BSTAGE;
#pragma unroll
        for (int u0 = 0; u0 < 2; ++u0) {
            const int u = tid + u0 * 256;
            const int row = u >> 2, c16 = u & 3;
            const int m = m0 + row;
            const void* src = Ab + (long long)m * Kh + koff + c16 * 8;
            cp16(abase + taddr(row, c16), src, (m < M) ? 16 : 0);
        }
#pragma unroll
        for (int u0 = 0; u0 < 2; ++u0) {
            const int u = tid + u0 * 256;
            const int row = u >> 2, c16 = u & 3;
            const void* src = W + (long long)(n0 + row) * K + k0 + c16 * 8;
            cp16(bbase + taddr(row, c16), src, 16);
        }
    };

    issue_chunk(0, 0); CP_COMMIT();
    issue_chunk(1, 1); CP_COMMIT();

    for (int ch = 0; ch < nch; ++ch) {
        CP_WAIT1();
        __syncthreads();
        {
            const int nxt = ch + STAGES - 1;
            if (nxt < nch) issue_chunk(nxt, nxt % STAGES);
            CP_COMMIT();
        }

        const int st = ch % STAGES;
        const uint32_t aST = sbA + st * ASTAGE;
        const uint32_t bST = sbB + st * BSTAGE;

#pragma unroll
        for (int s = 0; s < 2; ++s) {
            const int cc = s * 2 + qsel;
            uint32_t ah[4][4], bh[2][4];
#pragma unroll
            for (int i = 0; i < 4; ++i)
                ldsm4(ah[i], aST + taddr(wm * 64 + i * 16 + qrow, cc));
#pragma unroll
            for (int p = 0; p < 2; ++p)
                ldsm4(bh[p], bST + taddr(wn * 32 + p * 16 + qrow, cc));
#pragma unroll
            for (int i = 0; i < 4; ++i) {
#pragma unroll
                for (int p = 0; p < 2; ++p) {
                    uint32_t f0[2] = { bh[p][0], bh[p][2] };
                    uint32_t f1[2] = { bh[p][1], bh[p][3] };
                    mma16816(acc[i][2 * p],     ah[i], f0);
                    mma16816(acc[i][2 * p + 1], ah[i], f1);
                }
            }
        }
    }
    __syncthreads();

    if (FUSED == 0) {
#pragma unroll
        for (int j = 0; j < 4; ++j) {
            const int nb = n0 + wn * 32 + j * 8 + (lane & 3) * 2;
            const float b0f = bias[nb], b1f = bias[nb + 1];
#pragma unroll
            for (int i = 0; i < 4; ++i) {
                const int r0 = m0 + wm * 64 + i * 16 + (lane >> 2);
                if (r0 < M) {
                    *(uint32_t*)(C + (long long)r0 * HDIM + nb) =
                        pack_h2(fmaxf(acc[i][j][0] + b0f, 0.f),
                                fmaxf(acc[i][j][1] + b1f, 0.f));
                }
                const int r1 = r0 + 8;
                if (r1 < M) {
                    *(uint32_t*)(C + (long long)r1 * HDIM + nb) =
                        pack_h2(fmaxf(acc[i][j][2] + b0f, 0.f),
                                fmaxf(acc[i][j][3] + b1f, 0.f));
                }
            }
        }
    } else {
#pragma unroll
        for (int i = 0; i < 4; ++i) {
            float p0 = 0.f, p1 = 0.f;
#pragma unroll
            for (int j = 0; j < 4; ++j) {
                const int nb = n0 + wn * 32 + j * 8 + (lane & 3) * 2;
                const float b0f = bias[nb],  b1f = bias[nb + 1];
                const float w0 = __ldg(&Wo[nb]), w1 = __ldg(&Wo[nb + 1]);
                p0 += fmaxf(acc[i][j][0] + b0f, 0.f) * w0
                    + fmaxf(acc[i][j][1] + b1f, 0.f) * w1;
                p1 += fmaxf(acc[i][j][2] + b0f, 0.f) * w0
                    + fmaxf(acc[i][j][3] + b1f, 0.f) * w1;
            }
            p0 += __shfl_xor_sync(0xffffffffu, p0, 1);
            p0 += __shfl_xor_sync(0xffffffffu, p0, 2);
            p1 += __shfl_xor_sync(0xffffffffu, p1, 1);
            p1 += __shfl_xor_sync(0xffffffffu, p1, 2);
            if ((lane & 3) == 0) {
                const int r0 = m0 + wm * 64 + i * 16 + (lane >> 2);
                const int r1 = r0 + 8;
                if (r0 < M) atomicAdd(&outLogit[r0], p0);
                if (r1 < M) atomicAdd(&outLogit[r1], p1);
            }
        }
        // ---- completion counter: last n-band CTA applies sigmoid ----
        __threadfence();
        __syncthreads();
        __shared__ int sh_old;
        if (tid == 0) sh_old = atomicAdd(&done[blockIdx.x], 1);
        __syncthreads();
        if (sh_old == (int)gridDim.y - 1 && tid < 128) {
            const int m = m0 + tid;
            if (m < M) {
                volatile float* vo = outLogit;
                float z = vo[m];
                vo[m] = 1.0f / (1.0f + __expf(-z));
            }
        }
    }
}

// ---------------- launch ----------------

extern "C" void kernel_launch(void* const* d_in, const int* in_sizes, int n_in,
                              void* d_out, int out_size) {
    const float* x  = (const float*)d_in[0];
    const int*   ei = (const int*)  d_in[1];
    const float* W1 = (const float*)d_in[2];
    const float* b1 = (const float*)d_in[3];
    const float* W2 = (const float*)d_in[4];
    const float* b2 = (const float*)d_in[5];
    const float* Wo = (const float*)d_in[6];
    const float* bo = (const float*)d_in[7];
    float* out = (float*)d_out;

    const int N = in_sizes[0] / FDIM;
    const int E = in_sizes[1] / 2;
    const int* src = ei;
    const int* dst = ei + E;

    float *inv;
    __half *xh, *ag1, *h1, *ag2, *w1h, *w2h;
    int *aux, *off, *eid;
    cudaGetSymbolAddress((void**)&inv, g_inv);
    cudaGetSymbolAddress((void**)&xh,  g_xh);
    cudaGetSymbolAddress((void**)&ag1, g_ag1);
    cudaGetSymbolAddress((void**)&h1,  g_h1);
    cudaGetSymbolAddress((void**)&ag2, g_ag2);
    cudaGetSymbolAddress((void**)&w1h, g_w1h);
    cudaGetSymbolAddress((void**)&w2h, g_w2h);
    cudaGetSymbolAddress((void**)&aux, g_aux);
    cudaGetSymbolAddress((void**)&off, g_off);
    cudaGetSymbolAddress((void**)&eid, g_eid);

    const int nscan = (N + SCANB - 1) / SCANB;
    int* cnt   = aux;
    int* state = aux + MAXN;
    int* done  = aux + MAXN + NSCANB;

    cudaFuncSetAttribute(gemm_f16<0>, cudaFuncAttributeMaxDynamicSharedMemorySize, SMEM_TOT);
    cudaFuncSetAttribute(gemm_f16<1>, cudaFuncAttributeMaxDynamicSharedMemorySize, SMEM_TOT);

    const int T = 256;

    // ---- converts + aux clear ----
    const int nx4  = N * FDIM / 4;
    const int nw14 = HDIM * 2 * FDIM / 4;
    const int nw24 = HDIM * 2 * HDIM / 4;
    const int naux = MAXN + NSCANB + NDONE;
    const int tot  = nx4 + nw14 + nw24 + naux;
    tohalf_all<<<(tot + T - 1) / T, T>>>(x, xh, nx4, W1, w1h, nw14, W2, w2h, nw24, aux, naux);

    // ---- CSR build ----
    count_kernel<<<(E + T - 1) / T, T>>>(dst, E, cnt);
    scan_fused<<<nscan, SCANB>>>(cnt, off, inv, state, N, nscan);
    fill_kernel<<<(E + T - 1) / T, T>>>(src, dst, E, off, cnt, eid);

    // ---- layer 1 ----
    gather_f16<16><<<(N + 15) / 16, 256>>>(xh, off, eid, inv, ag1, N, nullptr, nullptr);
    {
        dim3 grid((N + 127) / 128, HDIM / 128);
        gemm_f16<0><<<grid, 256, SMEM_TOT>>>(xh, ag1, w1h, b1, h1, nullptr, nullptr,
                                             nullptr, N, FDIM);
    }

    // ---- layer 2 (head + sigmoid fused; gather inits logits to bo) ----
    gather_f16<64><<<(N + 3) / 4, 256>>>(h1, off, eid, inv, ag2, N, bo, out);
    {
        dim3 grid((N + 127) / 128, HDIM / 128);
        gemm_f16<1><<<grid, 256, SMEM_TOT>>>(h1, ag2, w2h, b2, nullptr, Wo, out,
                                             done, N, HDIM);
    }
}